// round 10
// baseline (speedup 1.0000x reference)
#include <cuda_runtime.h>
#include <cuda_fp16.h>
#include <cstdint>

#define EPSILON_F 1e-9f
#define NQ 100
#define L_SEQ 512
#define THREADS 640               // 20 warps; reg ceiling 102/thr
#define DEPTH 5

// fp16 copy of eta, produced once per launch by convert_kernel
__device__ __align__(16) __half g_eta_h[131072];

__device__ __forceinline__ uint32_t smem_u32(const void* p) {
    uint32_t a;
    asm("{ .reg .u64 t; cvta.to.shared.u64 t, %1; cvt.u32.u64 %0, t; }"
        : "=r"(a) : "l"(p));
    return a;
}
__device__ __forceinline__ void mbar_init(uint32_t m, uint32_t cnt) {
    asm volatile("mbarrier.init.shared.b64 [%0], %1;" :: "r"(m), "r"(cnt) : "memory");
}
__device__ __forceinline__ void mbar_expect_tx(uint32_t m, uint32_t bytes) {
    asm volatile("mbarrier.arrive.expect_tx.shared.b64 _, [%0], %1;"
                 :: "r"(m), "r"(bytes) : "memory");
}
__device__ __forceinline__ void mbar_wait(uint32_t m, uint32_t parity) {
    asm volatile(
        "{\n\t.reg .pred P;\n\t"
        "LW_%=:\n\t"
        "mbarrier.try_wait.parity.acquire.cta.shared::cta.b64 P, [%0], %1, 0x989680;\n\t"
        "@P bra LD_%=;\n\t"
        "bra LW_%=;\n\t"
        "LD_%=:\n\t}"
        :: "r"(m), "r"(parity) : "memory");
}
__device__ __forceinline__ void bulk_g2s(uint32_t dst, const void* src,
                                         uint32_t bytes, uint32_t mbar) {
    asm volatile(
        "cp.async.bulk.shared::cluster.global.mbarrier::complete_tx::bytes "
        "[%0], [%1], %2, [%3];"
        :: "r"(dst), "l"(src), "r"(bytes), "r"(mbar) : "memory");
}

__global__ void convert_kernel(const float* __restrict__ eta, int V) {
    const int n2 = V >> 1;
    const float2* e2 = reinterpret_cast<const float2*>(eta);
    __half2* d2 = reinterpret_cast<__half2*>(g_eta_h);
    const int i = blockIdx.x * blockDim.x + threadIdx.x;
    if (i < n2) {
        float2 v = __ldg(e2 + i);
        d2[i] = __floats2half2_rn(v.x, v.y);
    }
    if (i == 0 && (V & 1))
        g_eta_h[V - 1] = __float2half_rn(__ldg(eta + V - 1));
}

// Persistent: 1 CTA/SM, 20 warps. fp16 table arrives in smem via ONE
// cp.async.bulk. Depth-5 register ring of index buffers: 20 warps x 5 rows
// x 512B = 50KB/SM of LDG in flight (covers loaded DRAM latency).
__global__ __launch_bounds__(THREADS, 1)
void gather_kernel(const int* __restrict__ idx,
                   const float* __restrict__ t_ptr,
                   float* __restrict__ out, int B, int V) {
    extern __shared__ __align__(16) unsigned char smem[];

    const uint32_t TBL = (uint32_t)((2 * V + 15) & ~15);
    __half* tbl = reinterpret_cast<__half*>(smem);
    float*  ws  = reinterpret_cast<float*>(smem + TBL);

    const uint32_t sbase = smem_u32(smem);
    const uint32_t m_tbl = sbase + TBL + 64;

    const int tid    = threadIdx.x;
    const int warp   = tid >> 5;
    const int lane   = tid & 31;
    const int warps  = blockDim.x >> 5;           // 20
    const int stride = gridDim.x * warps;

    const float t = __ldg(t_ptr);

    if (tid == 0) mbar_init(m_tbl, 1);

    // ---- prologue: issue DEPTH rows' index loads EARLY ----
    const int row0 = blockIdx.x * warps + warp;
    int4 buf0[4], buf1[4], buf2[4], buf3[4], buf4[4];
    #define PROLOAD(BUF, K)                                                   \
    {                                                                         \
        const int r = row0 + (K) * stride;                                    \
        if (r < B) {                                                          \
            const int4* p = reinterpret_cast<const int4*>(                    \
                idx + (size_t)r * L_SEQ);                                     \
            _Pragma("unroll")                                                 \
            for (int j = 0; j < 4; j++) BUF[j] = __ldcs(&p[j * 32 + lane]);   \
        }                                                                     \
    }
    PROLOAD(buf0, 0)
    PROLOAD(buf1, 1)
    PROLOAD(buf2, 2)
    PROLOAD(buf3, 3)
    PROLOAD(buf4, 4)
    #undef PROLOAD

    // ---- scalar part: trapz(exp(-E),E), warps 0-3 ----
    if (tid < 128) {
        float val = 0.0f;
        if (tid < NQ - 1) {
            float Ei = ((float)tid       * (1.0f / (NQ - 1))) * t;
            float Ej = ((float)(tid + 1) * (1.0f / (NQ - 1))) * t;
            val = 0.5f * (__expf(-Ei) + __expf(-Ej)) * (Ej - Ei);
        }
        #pragma unroll
        for (int off = 16; off; off >>= 1)
            val += __shfl_xor_sync(0xffffffffu, val, off);
        if (lane == 0) ws[warp] = val;
    }
    __syncthreads();                               // mbar init + ws visible

    // ---- one bulk copy brings the whole fp16 table into smem ----
    if (tid == 0) {
        mbar_expect_tx(m_tbl, TBL);
        bulk_g2s(sbase, g_eta_h, TBL, m_tbl);
    }

    const float base = (ws[0] + ws[1] + ws[2] + ws[3])
                     - 0.5f * t * logf(t + EPSILON_F);

    mbar_wait(m_tbl, 0);                           // table ready

    if (row0 >= B) return;
    int row = row0;

    // one pipeline stage: gather BUF's row, refill BUF from row+DEPTH*stride
    #define STAGE(BUF)                                                        \
    {                                                                         \
        float a = 0.0f, b = 0.0f;                                             \
        _Pragma("unroll")                                                     \
        for (int j = 0; j < 4; j++) {                                         \
            a += __half2float(tbl[BUF[j].x]);                                 \
            b += __half2float(tbl[BUF[j].y]);                                 \
            a += __half2float(tbl[BUF[j].z]);                                 \
            b += __half2float(tbl[BUF[j].w]);                                 \
        }                                                                     \
        const int pre = row + DEPTH * stride;                                 \
        if (pre < B) {                                                        \
            const int4* p = reinterpret_cast<const int4*>(                    \
                idx + (size_t)pre * L_SEQ);                                   \
            _Pragma("unroll")                                                 \
            for (int j = 0; j < 4; j++) BUF[j] = __ldcs(&p[j * 32 + lane]);   \
        }                                                                     \
        float s = a + b;                                                      \
        _Pragma("unroll")                                                     \
        for (int off = 16; off; off >>= 1)                                    \
            s += __shfl_xor_sync(0xffffffffu, s, off);                        \
        if (lane == 0) out[row] = s + base;                                   \
    }

    for (;;) {
        STAGE(buf0); row += stride; if (row >= B) break;
        STAGE(buf1); row += stride; if (row >= B) break;
        STAGE(buf2); row += stride; if (row >= B) break;
        STAGE(buf3); row += stride; if (row >= B) break;
        STAGE(buf4); row += stride; if (row >= B) break;
    }
    #undef STAGE
}

extern "C" void kernel_launch(void* const* d_in, const int* in_sizes, int n_in,
                              void* d_out, int out_size) {
    const int*   idx = (const int*)d_in[0];     // [B, 512] int32
    const float* eta = (const float*)d_in[1];   // [V] f32
    const float* t   = (const float*)d_in[2];   // scalar f32
    float* out = (float*)d_out;

    const int B = in_sizes[0] / L_SEQ;
    const int V = in_sizes[1];

    // one-wave convert: ceil((V/2)/256) blocks
    const int cb = ((V >> 1) + 255) / 256;
    convert_kernel<<<cb, 256>>>(eta, V);

    int dev = 0, sms = 148;
    cudaGetDevice(&dev);
    cudaDeviceGetAttribute(&sms, cudaDevAttrMultiProcessorCount, dev);

    const size_t TBL = (size_t)((2 * V + 15) & ~15);
    const size_t smem = TBL + 64 + 64;           // table + ws + mbar
    cudaFuncSetAttribute(gather_kernel,
                         cudaFuncAttributeMaxDynamicSharedMemorySize, (int)smem);

    gather_kernel<<<sms, THREADS, smem>>>(idx, t, out, B, V);
}

// round 12
// speedup vs baseline: 1.1756x; 1.1756x over previous
#include <cuda_runtime.h>
#include <cuda_fp16.h>
#include <cstdint>

#define EPSILON_F 1e-9f
#define NQ 100
#define L_SEQ 512
#define THREADS 768               // 24 warps; reg ceiling 84/thr
#define DEPTH 3

// fp16 copy of eta, produced once per launch by convert_kernel
__device__ __align__(16) __half g_eta_h[131072];

__device__ __forceinline__ uint32_t smem_u32(const void* p) {
    uint32_t a;
    asm("{ .reg .u64 t; cvta.to.shared.u64 t, %1; cvt.u32.u64 %0, t; }"
        : "=r"(a) : "l"(p));
    return a;
}
__device__ __forceinline__ void mbar_init(uint32_t m, uint32_t cnt) {
    asm volatile("mbarrier.init.shared.b64 [%0], %1;" :: "r"(m), "r"(cnt) : "memory");
}
__device__ __forceinline__ void mbar_expect_tx(uint32_t m, uint32_t bytes) {
    asm volatile("mbarrier.arrive.expect_tx.shared.b64 _, [%0], %1;"
                 :: "r"(m), "r"(bytes) : "memory");
}
__device__ __forceinline__ void mbar_wait(uint32_t m, uint32_t parity) {
    asm volatile(
        "{\n\t.reg .pred P;\n\t"
        "LW_%=:\n\t"
        "mbarrier.try_wait.parity.acquire.cta.shared::cta.b64 P, [%0], %1, 0x989680;\n\t"
        "@P bra LD_%=;\n\t"
        "bra LW_%=;\n\t"
        "LD_%=:\n\t}"
        :: "r"(m), "r"(parity) : "memory");
}
__device__ __forceinline__ void bulk_g2s(uint32_t dst, const void* src,
                                         uint32_t bytes, uint32_t mbar) {
    asm volatile(
        "cp.async.bulk.shared::cluster.global.mbarrier::complete_tx::bytes "
        "[%0], [%1], %2, [%3];"
        :: "r"(dst), "l"(src), "r"(bytes), "r"(mbar) : "memory");
}

__global__ void convert_kernel(const float* __restrict__ eta, int V) {
    const int n2 = V >> 1;
    const float2* e2 = reinterpret_cast<const float2*>(eta);
    __half2* d2 = reinterpret_cast<__half2*>(g_eta_h);
    const int i = blockIdx.x * blockDim.x + threadIdx.x;
    if (i < n2) {
        float2 v = __ldg(e2 + i);
        d2[i] = __floats2half2_rn(v.x, v.y);
    }
    if (i == 0 && (V & 1))
        g_eta_h[V - 1] = __float2half_rn(__ldg(eta + V - 1));
}

// Persistent: 1 CTA/SM, 24 warps, depth-3 register ring, fp16 table via one
// cp.async.bulk. Deferred reduction: stage k runs the 5-SHFL tree of stage
// k-1's sum concurrently with stage k's LDS gathers (tail off critical path).
__global__ __launch_bounds__(THREADS, 1)
void gather_kernel(const int* __restrict__ idx,
                   const float* __restrict__ t_ptr,
                   float* __restrict__ out, int B, int V) {
    extern __shared__ __align__(16) unsigned char smem[];

    const uint32_t TBL = (uint32_t)((2 * V + 15) & ~15);
    __half* tbl = reinterpret_cast<__half*>(smem);
    float*  ws  = reinterpret_cast<float*>(smem + TBL);

    const uint32_t sbase = smem_u32(smem);
    const uint32_t m_tbl = sbase + TBL + 64;

    const int tid    = threadIdx.x;
    const int warp   = tid >> 5;
    const int lane   = tid & 31;
    const int warps  = blockDim.x >> 5;           // 24
    const int stride = gridDim.x * warps;

    const float t = __ldg(t_ptr);

    if (tid == 0) mbar_init(m_tbl, 1);

    // ---- prologue: issue DEPTH rows' index loads EARLY ----
    const int row0 = blockIdx.x * warps + warp;
    int4 buf0[4], buf1[4], buf2[4];
    #define PROLOAD(BUF, K)                                                   \
    {                                                                         \
        const int r = row0 + (K) * stride;                                    \
        if (r < B) {                                                          \
            const int4* p = reinterpret_cast<const int4*>(                    \
                idx + (size_t)r * L_SEQ);                                     \
            _Pragma("unroll")                                                 \
            for (int j = 0; j < 4; j++) BUF[j] = __ldcs(&p[j * 32 + lane]);   \
        }                                                                     \
    }
    PROLOAD(buf0, 0)
    PROLOAD(buf1, 1)
    PROLOAD(buf2, 2)
    #undef PROLOAD

    // ---- scalar part: trapz(exp(-E),E), warps 0-3 ----
    if (tid < 128) {
        float val = 0.0f;
        if (tid < NQ - 1) {
            float Ei = ((float)tid       * (1.0f / (NQ - 1))) * t;
            float Ej = ((float)(tid + 1) * (1.0f / (NQ - 1))) * t;
            val = 0.5f * (__expf(-Ei) + __expf(-Ej)) * (Ej - Ei);
        }
        #pragma unroll
        for (int off = 16; off; off >>= 1)
            val += __shfl_xor_sync(0xffffffffu, val, off);
        if (lane == 0) ws[warp] = val;
    }
    __syncthreads();                               // mbar init + ws visible

    // ---- one bulk copy brings the whole fp16 table into smem ----
    if (tid == 0) {
        mbar_expect_tx(m_tbl, TBL);
        bulk_g2s(sbase, g_eta_h, TBL, m_tbl);
    }

    const float base = (ws[0] + ws[1] + ws[2] + ws[3])
                     - 0.5f * t * logf(t + EPSILON_F);

    mbar_wait(m_tbl, 0);                           // table ready

    if (row0 >= B) return;
    int row = row0;

    float pending = 0.0f;                          // previous stage's raw sum
    int pending_row = -1;

    // stage: gather BUF's row, refill BUF, reduce+store PREVIOUS row's sum
    #define STAGE(BUF)                                                        \
    {                                                                         \
        float a = 0.0f, b = 0.0f, c = 0.0f, d = 0.0f;                         \
        _Pragma("unroll")                                                     \
        for (int j = 0; j < 4; j++) {                                         \
            a += __half2float(tbl[BUF[j].x]);                                 \
            b += __half2float(tbl[BUF[j].y]);                                 \
            c += __half2float(tbl[BUF[j].z]);                                 \
            d += __half2float(tbl[BUF[j].w]);                                 \
        }                                                                     \
        const int pre = row + DEPTH * stride;                                 \
        if (pre < B) {                                                        \
            const int4* p = reinterpret_cast<const int4*>(                    \
                idx + (size_t)pre * L_SEQ);                                   \
            _Pragma("unroll")                                                 \
            for (int j = 0; j < 4; j++) BUF[j] = __ldcs(&p[j * 32 + lane]);   \
        }                                                                     \
        /* reduce previous stage's sum — independent of gathers above */      \
        float ps = pending;                                                   \
        _Pragma("unroll")                                                     \
        for (int off = 16; off; off >>= 1)                                    \
            ps += __shfl_xor_sync(0xffffffffu, ps, off);                      \
        if (lane == 0 && pending_row >= 0) out[pending_row] = ps + base;      \
        pending = (a + b) + (c + d);                                          \
        pending_row = row;                                                    \
    }

    for (;;) {
        STAGE(buf0); row += stride; if (row >= B) break;
        STAGE(buf1); row += stride; if (row >= B) break;
        STAGE(buf2); row += stride; if (row >= B) break;
    }
    #undef STAGE

    // epilogue: flush the last pending row
    #pragma unroll
    for (int off = 16; off; off >>= 1)
        pending += __shfl_xor_sync(0xffffffffu, pending, off);
    if (lane == 0 && pending_row >= 0) out[pending_row] = pending + base;
}

extern "C" void kernel_launch(void* const* d_in, const int* in_sizes, int n_in,
                              void* d_out, int out_size) {
    const int*   idx = (const int*)d_in[0];     // [B, 512] int32
    const float* eta = (const float*)d_in[1];   // [V] f32
    const float* t   = (const float*)d_in[2];   // scalar f32
    float* out = (float*)d_out;

    const int B = in_sizes[0] / L_SEQ;
    const int V = in_sizes[1];

    // one-wave convert: ceil((V/2)/256) blocks
    const int cb = ((V >> 1) + 255) / 256;
    convert_kernel<<<cb, 256>>>(eta, V);

    int dev = 0, sms = 148;
    cudaGetDevice(&dev);
    cudaDeviceGetAttribute(&sms, cudaDevAttrMultiProcessorCount, dev);

    const size_t TBL = (size_t)((2 * V + 15) & ~15);
    const size_t smem = TBL + 64 + 64;           // table + ws + mbar
    cudaFuncSetAttribute(gather_kernel,
                         cudaFuncAttributeMaxDynamicSharedMemorySize, (int)smem);

    gather_kernel<<<sms, THREADS, smem>>>(idx, t, out, B, V);
}

// round 13
// speedup vs baseline: 1.2688x; 1.0793x over previous
#include <cuda_runtime.h>
#include <cuda_fp16.h>
#include <cstdint>

#define EPSILON_F 1e-9f
#define NQ 100
#define L_SEQ 512
#define THREADS 768               // 24 warps; reg ceiling 84/thr
#define DEPTH 3
#define PF_DIST 8                 // prefetch-to-L2 distance (rows, per warp)

// fp16 copy of eta, produced once per launch by convert_kernel
__device__ __align__(16) __half g_eta_h[131072];

__device__ __forceinline__ uint32_t smem_u32(const void* p) {
    uint32_t a;
    asm("{ .reg .u64 t; cvta.to.shared.u64 t, %1; cvt.u32.u64 %0, t; }"
        : "=r"(a) : "l"(p));
    return a;
}
__device__ __forceinline__ void mbar_init(uint32_t m, uint32_t cnt) {
    asm volatile("mbarrier.init.shared.b64 [%0], %1;" :: "r"(m), "r"(cnt) : "memory");
}
__device__ __forceinline__ void mbar_expect_tx(uint32_t m, uint32_t bytes) {
    asm volatile("mbarrier.arrive.expect_tx.shared.b64 _, [%0], %1;"
                 :: "r"(m), "r"(bytes) : "memory");
}
__device__ __forceinline__ void mbar_wait(uint32_t m, uint32_t parity) {
    asm volatile(
        "{\n\t.reg .pred P;\n\t"
        "LW_%=:\n\t"
        "mbarrier.try_wait.parity.acquire.cta.shared::cta.b64 P, [%0], %1, 0x989680;\n\t"
        "@P bra LD_%=;\n\t"
        "bra LW_%=;\n\t"
        "LD_%=:\n\t}"
        :: "r"(m), "r"(parity) : "memory");
}
__device__ __forceinline__ void bulk_g2s(uint32_t dst, const void* src,
                                         uint32_t bytes, uint32_t mbar) {
    asm volatile(
        "cp.async.bulk.shared::cluster.global.mbarrier::complete_tx::bytes "
        "[%0], [%1], %2, [%3];"
        :: "r"(dst), "l"(src), "r"(bytes), "r"(mbar) : "memory");
}

__global__ void convert_kernel(const float* __restrict__ eta, int V) {
    const int n2 = V >> 1;
    const float2* e2 = reinterpret_cast<const float2*>(eta);
    __half2* d2 = reinterpret_cast<__half2*>(g_eta_h);
    const int i = blockIdx.x * blockDim.x + threadIdx.x;
    if (i < n2) {
        float2 v = __ldg(e2 + i);
        d2[i] = __floats2half2_rn(v.x, v.y);
    }
    if (i == 0 && (V & 1))
        g_eta_h[V - 1] = __float2half_rn(__ldg(eta + V - 1));
}

// Persistent: 1 CTA/SM, 24 warps, depth-3 register ring, fp16 table via one
// cp.async.bulk. prefetch.global.L2 runs 8 rows ahead so the architectural
// refill LDGs hit L2 (~250 cyc) instead of DRAM (~600-800 cyc) -> depth-3
// coverage suffices and warps stop scoreboard-stalling.
__global__ __launch_bounds__(THREADS, 1)
void gather_kernel(const int* __restrict__ idx,
                   const float* __restrict__ t_ptr,
                   float* __restrict__ out, int B, int V) {
    extern __shared__ __align__(16) unsigned char smem[];

    const uint32_t TBL = (uint32_t)((2 * V + 15) & ~15);
    __half* tbl = reinterpret_cast<__half*>(smem);
    float*  ws  = reinterpret_cast<float*>(smem + TBL);

    const uint32_t sbase = smem_u32(smem);
    const uint32_t m_tbl = sbase + TBL + 64;

    const int tid    = threadIdx.x;
    const int warp   = tid >> 5;
    const int lane   = tid & 31;
    const int warps  = blockDim.x >> 5;           // 24
    const int stride = gridDim.x * warps;

    const float t = __ldg(t_ptr);

    if (tid == 0) mbar_init(m_tbl, 1);

    // ---- prologue: issue DEPTH rows' index loads EARLY ----
    const int row0 = blockIdx.x * warps + warp;
    int4 buf0[4], buf1[4], buf2[4];
    #define PROLOAD(BUF, K)                                                   \
    {                                                                         \
        const int r = row0 + (K) * stride;                                    \
        if (r < B) {                                                          \
            const int4* p = reinterpret_cast<const int4*>(                    \
                idx + (size_t)r * L_SEQ);                                     \
            _Pragma("unroll")                                                 \
            for (int j = 0; j < 4; j++) BUF[j] = __ldcs(&p[j * 32 + lane]);   \
        }                                                                     \
    }
    PROLOAD(buf0, 0)
    PROLOAD(buf1, 1)
    PROLOAD(buf2, 2)
    #undef PROLOAD

    // prefetch rows DEPTH..PF_DIST-1 to L2 (lead for the first refills)
    for (int k = DEPTH; k < PF_DIST; k++) {
        const long r = (long)row0 + (long)k * stride;
        if (r < B) {
            const char* pp = reinterpret_cast<const char*>(idx + (size_t)r * L_SEQ)
                           + (lane << 6);
            asm volatile("prefetch.global.L2 [%0];" :: "l"(pp));
        }
    }

    // ---- scalar part: trapz(exp(-E),E), warps 0-3 ----
    if (tid < 128) {
        float val = 0.0f;
        if (tid < NQ - 1) {
            float Ei = ((float)tid       * (1.0f / (NQ - 1))) * t;
            float Ej = ((float)(tid + 1) * (1.0f / (NQ - 1))) * t;
            val = 0.5f * (__expf(-Ei) + __expf(-Ej)) * (Ej - Ei);
        }
        #pragma unroll
        for (int off = 16; off; off >>= 1)
            val += __shfl_xor_sync(0xffffffffu, val, off);
        if (lane == 0) ws[warp] = val;
    }
    __syncthreads();                               // mbar init + ws visible

    // ---- one bulk copy brings the whole fp16 table into smem ----
    if (tid == 0) {
        mbar_expect_tx(m_tbl, TBL);
        bulk_g2s(sbase, g_eta_h, TBL, m_tbl);
    }

    const float base = (ws[0] + ws[1] + ws[2] + ws[3])
                     - 0.5f * t * logf(t + EPSILON_F);

    mbar_wait(m_tbl, 0);                           // table ready

    if (row0 >= B) return;
    int row = row0;

    // stage: prefetch row+PF to L2, gather BUF's row, refill BUF (L2 hit)
    #define STAGE(BUF)                                                        \
    {                                                                         \
        const long pf = (long)row + (long)PF_DIST * stride;                   \
        if (pf < B) {                                                         \
            const char* pp = reinterpret_cast<const char*>(                   \
                idx + (size_t)pf * L_SEQ) + (lane << 6);                      \
            asm volatile("prefetch.global.L2 [%0];" :: "l"(pp));              \
        }                                                                     \
        float a = 0.0f, b = 0.0f, c = 0.0f, d = 0.0f;                         \
        _Pragma("unroll")                                                     \
        for (int j = 0; j < 4; j++) {                                         \
            a += __half2float(tbl[BUF[j].x]);                                 \
            b += __half2float(tbl[BUF[j].y]);                                 \
            c += __half2float(tbl[BUF[j].z]);                                 \
            d += __half2float(tbl[BUF[j].w]);                                 \
        }                                                                     \
        const int pre = row + DEPTH * stride;                                 \
        if (pre < B) {                                                        \
            const int4* p = reinterpret_cast<const int4*>(                    \
                idx + (size_t)pre * L_SEQ);                                   \
            _Pragma("unroll")                                                 \
            for (int j = 0; j < 4; j++) BUF[j] = __ldcs(&p[j * 32 + lane]);   \
        }                                                                     \
        float s = (a + b) + (c + d);                                          \
        _Pragma("unroll")                                                     \
        for (int off = 16; off; off >>= 1)                                    \
            s += __shfl_xor_sync(0xffffffffu, s, off);                        \
        if (lane == 0) out[row] = s + base;                                   \
    }

    for (;;) {
        STAGE(buf0); row += stride; if (row >= B) break;
        STAGE(buf1); row += stride; if (row >= B) break;
        STAGE(buf2); row += stride; if (row >= B) break;
    }
    #undef STAGE
}

extern "C" void kernel_launch(void* const* d_in, const int* in_sizes, int n_in,
                              void* d_out, int out_size) {
    const int*   idx = (const int*)d_in[0];     // [B, 512] int32
    const float* eta = (const float*)d_in[1];   // [V] f32
    const float* t   = (const float*)d_in[2];   // scalar f32
    float* out = (float*)d_out;

    const int B = in_sizes[0] / L_SEQ;
    const int V = in_sizes[1];

    // one-wave convert: ceil((V/2)/256) blocks
    const int cb = ((V >> 1) + 255) / 256;
    convert_kernel<<<cb, 256>>>(eta, V);

    int dev = 0, sms = 148;
    cudaGetDevice(&dev);
    cudaDeviceGetAttribute(&sms, cudaDevAttrMultiProcessorCount, dev);

    const size_t TBL = (size_t)((2 * V + 15) & ~15);
    const size_t smem = TBL + 64 + 64;           // table + ws + mbar
    cudaFuncSetAttribute(gather_kernel,
                         cudaFuncAttributeMaxDynamicSharedMemorySize, (int)smem);

    gather_kernel<<<sms, THREADS, smem>>>(idx, t, out, B, V);
}